// round 11
// baseline (speedup 1.0000x reference)
#include <cuda_runtime.h>
#include <cuda_bf16.h>

#define TOKENS 32768
#define DDIM 1024
#define RDIM 48
#define MTILE 256
#define THREADS 512
#define NCTAS (TOKENS / MTILE)   // 128 CTAs -> one wave
#define KC 16
#define NCH (DDIM / KC)          // 64 chunks per phase

#define GWST 1032                // bf16 elems per gw row (2064B; /16=129 -> conflict-free LDSM)
#define WUST 56                  // bf16 elems per wu row (112B; /16=7 -> conflict-free LDSM)
#define XROW 20                  // fp32 elems per x-stage row (80B; 16B-aligned for cp16)
#define YS_STRIDE 52             // bf16
#define H2_STRIDE 52             // bf16

#define WBLK (16 * XROW * 4)     // 1280 B per warp per stage
#define XSTG (16 * WBLK)         // 20480 B per stage
#define NSTAGE 3

// ---- smem layout (bytes) ----
#define OFF_W   0
#define SZ_W    (DDIM * WUST * 2)            // 114688 (>= gw 48*2064 = 99072)
#define OFF_XST (OFF_W + SZ_W)               // 3 stages: 61440
#define OFF_Y   (OFF_XST + XSTG)             // y overlays stages 1-2 (26624 <= 40960)
#define OFF_H2  (OFF_XST + NSTAGE * XSTG)    // 26624
#define OFF_SUM (OFF_H2 + MTILE * H2_STRIDE * 2)
#define OFF_SSQ (OFF_SUM + MTILE * 4)
#define OFF_SGW (OFF_SSQ + MTILE * 4)
#define OFF_CB  (OFF_SGW + RDIM * 4)
#define OFF_C48 (OFF_CB + RDIM * 4)
#define OFF_A48 (OFF_C48 + RDIM * 4)
#define SMEM_TOTAL (OFF_A48 + RDIM * RDIM * 4)   // 214592 <= 232448

__device__ __forceinline__ float gelu_exact(float v) {
    return 0.5f * v * (1.0f + erff(v * 0.70710678118654752440f));
}

__device__ __forceinline__ void mma_bf16(float* c, unsigned a0, unsigned a1, unsigned a2,
                                         unsigned a3, unsigned b0, unsigned b1) {
    asm volatile(
        "mma.sync.aligned.m16n8k16.row.col.f32.bf16.bf16.f32 "
        "{%0,%1,%2,%3}, {%4,%5,%6,%7}, {%8,%9}, {%0,%1,%2,%3};\n"
        : "+f"(c[0]), "+f"(c[1]), "+f"(c[2]), "+f"(c[3])
        : "r"(a0), "r"(a1), "r"(a2), "r"(a3), "r"(b0), "r"(b1));
}

__device__ __forceinline__ void ldsm_x4(unsigned* r, unsigned addr) {
    asm volatile("ldmatrix.sync.aligned.m8n8.x4.shared.b16 {%0,%1,%2,%3}, [%4];"
                 : "=r"(r[0]), "=r"(r[1]), "=r"(r[2]), "=r"(r[3]) : "r"(addr));
}

__device__ __forceinline__ unsigned pack2(float a, float b) {
    __nv_bfloat162 p = __floats2bfloat162_rn(a, b);
    return *(unsigned*)&p;
}
__device__ __forceinline__ uint2 pack_bf16x4(float a, float b, float c, float d) {
    uint2 pk;
    pk.x = pack2(a, b);
    pk.y = pack2(c, d);
    return pk;
}

__device__ __forceinline__ void cp16(unsigned dst, const void* src) {
    asm volatile("cp.async.cg.shared.global [%0], [%1], 16;\n" :: "r"(dst), "l"(src));
}
__device__ __forceinline__ void cp_commit() {
    asm volatile("cp.async.commit_group;\n");
}
template <int N>
__device__ __forceinline__ void cp_wait() {
    asm volatile("cp.async.wait_group %0;\n" :: "n"(N));
}

// ============================================================================
// Single fully-fused kernel. Barrier-free mainloops: resident weights in smem,
// per-warp private x pipelines (each warp owns its 16 token rows).
// ============================================================================
__global__ void __launch_bounds__(THREADS, 1) fused_kernel(
    const float* __restrict__ x, const float* __restrict__ gamma,
    const float* __restrict__ beta, const float* __restrict__ w_down,
    const float* __restrict__ w_to_mv, const float* __restrict__ w_equi,
    const float* __restrict__ b_equi, const float* __restrict__ w_from_mv,
    const float* __restrict__ w_up, const float* __restrict__ scale_p,
    float* __restrict__ out)
{
    extern __shared__ char smem[];
    const unsigned sbase = (unsigned)__cvta_generic_to_shared(smem);
    __nv_bfloat16* y_s  = (__nv_bfloat16*)(smem + OFF_Y);
    __nv_bfloat16* h2_s = (__nv_bfloat16*)(smem + OFF_H2);
    float* sum_s   = (float*)(smem + OFF_SUM);
    float* sumsq_s = (float*)(smem + OFF_SSQ);
    float* sumgw_s = (float*)(smem + OFF_SGW);
    float* cb_s    = (float*)(smem + OFF_CB);
    float* c48_s   = (float*)(smem + OFF_C48);
    float* A48T_s  = (float*)(smem + OFF_A48);

    const int tid = threadIdx.x, lane = tid & 31, warp = tid >> 5;
    const int g = lane >> 2, t4 = lane & 3;
    const int tok0 = blockIdx.x * MTILE;
    const int mrow = warp * 16;

    // LDSM lane mapping
    const int bn = ((lane >> 4) << 3) + (lane & 7);
    const int kh = (lane >> 3) & 1;

    // per-warp x cp mapping: 2 ops/lane cover 16 rows x 16 cols fp32
    const int xr0 = lane >> 2, xq0 = lane & 3;          // op0: rows 0..7
    const int xr1 = 8 + (lane >> 2), xq1 = lane & 3;    // op1: rows 8..15
    const unsigned mystage = sbase + OFF_XST + warp * WBLK;
    const float* xwarp = x + (size_t)(tok0 + mrow) * DDIM;

    // ---- issue phase-A chunks 0,1 (per-warp private) ----
    #pragma unroll
    for (int kn = 0; kn < 2; kn++) {
        unsigned d = mystage + kn * XSTG;
        const float* s = xwarp + kn * KC;
        cp16(d + xr0 * 80 + xq0 * 16, s + (size_t)xr0 * DDIM + xq0 * 4);
        cp16(d + xr1 * 80 + xq1 * 16, s + (size_t)xr1 * DDIM + xq1 * 4);
        cp_commit();
    }

    // ---- stage gw = bf16(gamma (*) w_down) resident (L2-broadcast hot) ----
    {
        const float4* wd4 = (const float4*)w_down;
        const float4* g4  = (const float4*)gamma;
        for (int i = tid; i < RDIM * (DDIM / 4); i += THREADS) {
            int r = i >> 8, c4 = i & 255;
            float4 w = wd4[i];
            float4 gv = g4[c4];
            *(uint2*)(smem + OFF_W + r * (GWST * 2) + c4 * 8) =
                pack_bf16x4(w.x * gv.x, w.y * gv.y, w.z * gv.z, w.w * gv.w);
        }
    }
    __syncthreads();   // gw_s visible (ldsm + sumgw)

    // ---- per-CTA prep: sumgw (from staged bf16), cb, c48, A48T ----
    #pragma unroll 1
    for (int rr = 0; rr < 3; rr++) {
        int r = warp + rr * 16;
        float sg = 0.f, scb = 0.f;
        #pragma unroll
        for (int it = 0; it < 8; it++) {
            int d = it * 128 + lane * 4;
            uint2 pk = *(const uint2*)(smem + OFF_W + r * (GWST * 2) + d * 2);
            __nv_bfloat162 b0 = *(__nv_bfloat162*)&pk.x;
            __nv_bfloat162 b1 = *(__nv_bfloat162*)&pk.y;
            sg += __bfloat162float(b0.x) + __bfloat162float(b0.y)
                + __bfloat162float(b1.x) + __bfloat162float(b1.y);
            float4 wv = *(const float4*)(w_down + (size_t)r * DDIM + d);
            float4 bv = *(const float4*)(beta + d);
            scb += wv.x * bv.x + wv.y * bv.y + wv.z * bv.z + wv.w * bv.w;
        }
        #pragma unroll
        for (int off = 16; off; off >>= 1) {
            sg  += __shfl_xor_sync(0xffffffffu, sg, off);
            scb += __shfl_xor_sync(0xffffffffu, scb, off);
        }
        if (lane == 0) { sumgw_s[r] = sg; cb_s[r] = scb; }
    }
    for (int i = tid; i < RDIM; i += THREADS)
        c48_s[i] = __ldg(w_from_mv + i * 16) * __ldg(b_equi);
    for (int i = tid; i < RDIM * RDIM; i += THREADS) {
        int rp = i / RDIM, r = i - rp * RDIM;
        float a = 0.f;
        #pragma unroll
        for (int m = 0; m < 16; m++) {
            int gidx = (m == 0) ? 0 : (m < 5) ? 1 : (m < 11) ? 2 : (m < 15) ? 3 : 4;
            a += __ldg(w_from_mv + r * 16 + m) * __ldg(w_equi + gidx)
               * __ldg(w_to_mv + m * RDIM + rp);
        }
        A48T_s[i] = a;
    }

    // ---- phase A mainloop: per-warp, barrier-free ----
    float acc[6][4];
    #pragma unroll
    for (int j = 0; j < 6; j++)
        #pragma unroll
        for (int q = 0; q < 4; q++) acc[j][q] = 0.f;
    float ps0 = 0.f, pss0 = 0.f, ps1 = 0.f, pss1 = 0.f;

    #pragma unroll 2
    for (int kc = 0; kc < NCH; kc++) {
        int kn = kc + 2;
        if (kn < NCH) {
            unsigned d = mystage + (kn % NSTAGE) * XSTG;
            const float* s = xwarp + kn * KC;
            cp16(d + xr0 * 80 + xq0 * 16, s + (size_t)xr0 * DDIM + xq0 * 4);
            cp16(d + xr1 * 80 + xq1 * 16, s + (size_t)xr1 * DDIM + xq1 * 4);
        }
        cp_commit();
        cp_wait<2>();
        __syncwarp();

        const float* xs = (const float*)(smem + OFF_XST + (kc % NSTAGE) * XSTG + warp * WBLK);
        float2 p00 = *(const float2*)(xs + g * XROW + t4 * 2);
        float2 p10 = *(const float2*)(xs + (g + 8) * XROW + t4 * 2);
        float2 p01 = *(const float2*)(xs + g * XROW + 8 + t4 * 2);
        float2 p11 = *(const float2*)(xs + (g + 8) * XROW + 8 + t4 * 2);
        ps0  += (p00.x + p00.y) + (p01.x + p01.y);
        pss0 += (p00.x * p00.x + p00.y * p00.y) + (p01.x * p01.x + p01.y * p01.y);
        ps1  += (p10.x + p10.y) + (p11.x + p11.y);
        pss1 += (p10.x * p10.x + p10.y * p10.y) + (p11.x * p11.x + p11.y * p11.y);
        unsigned a0 = pack2(p00.x, p00.y);
        unsigned a1 = pack2(p10.x, p10.y);
        unsigned a2 = pack2(p01.x, p01.y);
        unsigned a3 = pack2(p11.x, p11.y);

        unsigned wb = sbase + OFF_W + bn * (GWST * 2) + kh * 16 + kc * 32;
        unsigned br[3][4];
        #pragma unroll
        for (int p = 0; p < 3; p++)
            ldsm_x4(br[p], wb + p * 16 * (GWST * 2));
        #pragma unroll
        for (int j = 0; j < 6; j++)
            mma_bf16(acc[j], a0, a1, a2, a3, br[j >> 1][(j & 1) * 2], br[j >> 1][(j & 1) * 2 + 1]);
    }

    // ---- stats reduce + prefetch C chunk 0 (stage 0 only; y overlays 1-2) ----
    #pragma unroll
    for (int off = 1; off <= 2; off <<= 1) {
        ps0  += __shfl_xor_sync(0xffffffffu, ps0, off);
        pss0 += __shfl_xor_sync(0xffffffffu, pss0, off);
        ps1  += __shfl_xor_sync(0xffffffffu, ps1, off);
        pss1 += __shfl_xor_sync(0xffffffffu, pss1, off);
    }
    if (t4 == 0) {
        sum_s[mrow + g] = ps0;     sumsq_s[mrow + g] = pss0;
        sum_s[mrow + g + 8] = ps1; sumsq_s[mrow + g + 8] = pss1;
    }
    {
        unsigned d = mystage;                     // stage 0
        const float* s = xwarp;                   // C chunk 0 = cols 0..15
        cp16(d + xr0 * 80 + xq0 * 16, s + (size_t)xr0 * DDIM + xq0 * 4);
        cp16(d + xr1 * 80 + xq1 * 16, s + (size_t)xr1 * DDIM + xq1 * 4);
        cp_commit();
    }
    __syncthreads();
    if (tid < MTILE) {
        float mu  = sum_s[tid] * (1.0f / DDIM);
        float var = sumsq_s[tid] * (1.0f / DDIM) - mu * mu;
        sum_s[tid]   = mu;
        sumsq_s[tid] = rsqrtf(var + 1e-5f);
    }
    // ---- stage wu = bf16(w_up) resident (gw dead now) ----
    {
        const float4* wu4 = (const float4*)w_up;
        for (int i = tid; i < DDIM * (RDIM / 4); i += THREADS) {
            int d = i / 12, q = i - d * 12;
            float4 v = wu4[i];
            *(uint2*)(smem + OFF_W + d * (WUST * 2) + q * 8) =
                pack_bf16x4(v.x, v.y, v.z, v.w);
        }
    }
    __syncthreads();

    // ---- y = gelu(rinv*(acc - mu*sumgw) + cb) -> bf16 ----
    {
        int r0 = mrow + g, r1 = r0 + 8;
        float mu0 = sum_s[r0], ri0 = sumsq_s[r0];
        float mu1 = sum_s[r1], ri1 = sumsq_s[r1];
        #pragma unroll
        for (int j = 0; j < 6; j++) {
            int c0 = j * 8 + t4 * 2, c1 = c0 + 1;
            float y00 = gelu_exact(ri0 * (acc[j][0] - mu0 * sumgw_s[c0]) + cb_s[c0]);
            float y01 = gelu_exact(ri0 * (acc[j][1] - mu0 * sumgw_s[c1]) + cb_s[c1]);
            float y10 = gelu_exact(ri1 * (acc[j][2] - mu1 * sumgw_s[c0]) + cb_s[c0]);
            float y11 = gelu_exact(ri1 * (acc[j][3] - mu1 * sumgw_s[c1]) + cb_s[c1]);
            *(__nv_bfloat162*)(y_s + r0 * YS_STRIDE + c0) = __floats2bfloat162_rn(y00, y01);
            *(__nv_bfloat162*)(y_s + r1 * YS_STRIDE + c0) = __floats2bfloat162_rn(y10, y11);
        }
    }
    __syncthreads();

    // ---- middle: h2 = gelu(A48 @ y + c48) -> bf16 ----
    {
        int t = tid >> 1;
        int rbase = (tid & 1) * 24;
        const __nv_bfloat16* yrow = y_s + t * YS_STRIDE;
        float h2v[24];
        #pragma unroll
        for (int r = 0; r < 24; r++) h2v[r] = c48_s[rbase + r];
        #pragma unroll 4
        for (int kp2 = 0; kp2 < RDIM / 2; kp2++) {
            __nv_bfloat162 yp = *(const __nv_bfloat162*)(yrow + kp2 * 2);
            float yv0 = __bfloat162float(yp.x), yv1 = __bfloat162float(yp.y);
            const float* a0 = A48T_s + (kp2 * 2) * RDIM + rbase;
            const float* a1 = a0 + RDIM;
            #pragma unroll
            for (int r = 0; r < 24; r++) h2v[r] += yv0 * a0[r] + yv1 * a1[r];
        }
        __nv_bfloat16* op = h2_s + t * H2_STRIDE + rbase;
        #pragma unroll
        for (int r = 0; r < 24; r += 2) {
            __nv_bfloat162 p = __floats2bfloat162_rn(gelu_exact(h2v[r]), gelu_exact(h2v[r + 1]));
            *(__nv_bfloat162*)(op + r) = p;
        }
    }
    __syncthreads();   // h2 + wu visible; y/stage1-2 dead

    // ---- phase C: out = x + scale*(h2 @ wu^T), per-warp barrier-free ----
    float scale = __ldg(scale_p);
    unsigned afr[3][4];
    #pragma unroll
    for (int kk = 0; kk < 3; kk++) {
        afr[kk][0] = *(const unsigned*)(h2_s + (mrow + g) * H2_STRIDE + kk * 16 + t4 * 2);
        afr[kk][1] = *(const unsigned*)(h2_s + (mrow + g + 8) * H2_STRIDE + kk * 16 + t4 * 2);
        afr[kk][2] = *(const unsigned*)(h2_s + (mrow + g) * H2_STRIDE + kk * 16 + 8 + t4 * 2);
        afr[kk][3] = *(const unsigned*)(h2_s + (mrow + g + 8) * H2_STRIDE + kk * 16 + 8 + t4 * 2);
    }
    {   // C chunk 1 into stage 1 (safe now)
        unsigned d = mystage + 1 * XSTG;
        const float* s = xwarp + 1 * KC;
        cp16(d + xr0 * 80 + xq0 * 16, s + (size_t)xr0 * DDIM + xq0 * 4);
        cp16(d + xr1 * 80 + xq1 * 16, s + (size_t)xr1 * DDIM + xq1 * 4);
        cp_commit();
    }

    #pragma unroll 2
    for (int nc = 0; nc < NCH; nc++) {
        int nn = nc + 2;
        if (nn < NCH) {
            unsigned d = mystage + (nn % NSTAGE) * XSTG;
            const float* s = xwarp + nn * KC;
            cp16(d + xr0 * 80 + xq0 * 16, s + (size_t)xr0 * DDIM + xq0 * 4);
            cp16(d + xr1 * 80 + xq1 * 16, s + (size_t)xr1 * DDIM + xq1 * 4);
        }
        cp_commit();
        cp_wait<2>();
        __syncwarp();

        const float* xs = (const float*)(smem + OFF_XST + (nc % NSTAGE) * XSTG + warp * WBLK);
        unsigned wub = sbase + OFF_W + (nc * 16 + bn) * (WUST * 2) + kh * 16;
        unsigned br[3][4];
        #pragma unroll
        for (int kk = 0; kk < 3; kk++)
            ldsm_x4(br[kk], wub + kk * 32);

        float uacc[2][4];
        #pragma unroll
        for (int j = 0; j < 2; j++)
            #pragma unroll
            for (int q = 0; q < 4; q++) uacc[j][q] = 0.f;
        #pragma unroll
        for (int kk = 0; kk < 3; kk++)
            #pragma unroll
            for (int j = 0; j < 2; j++)
                mma_bf16(uacc[j], afr[kk][0], afr[kk][1], afr[kk][2], afr[kk][3],
                         br[kk][j * 2], br[kk][j * 2 + 1]);

        size_t row0 = (size_t)(tok0 + mrow + g) * DDIM + nc * 16;
        size_t row1 = row0 + 8 * (size_t)DDIM;
        #pragma unroll
        for (int j = 0; j < 2; j++) {
            int lc = j * 8 + t4 * 2;
            float2 xv0 = *(const float2*)(xs + g * XROW + lc);
            float2 xv1 = *(const float2*)(xs + (g + 8) * XROW + lc);
            float2 o0 = make_float2(xv0.x + scale * uacc[j][0], xv0.y + scale * uacc[j][1]);
            float2 o1 = make_float2(xv1.x + scale * uacc[j][2], xv1.y + scale * uacc[j][3]);
            __stcs((float2*)(out + row0 + lc), o0);
            __stcs((float2*)(out + row1 + lc), o1);
        }
    }
}

extern "C" void kernel_launch(void* const* d_in, const int* in_sizes, int n_in,
                              void* d_out, int out_size) {
    const float* x         = (const float*)d_in[0];
    const float* gamma     = (const float*)d_in[1];
    const float* beta      = (const float*)d_in[2];
    const float* w_down    = (const float*)d_in[3];
    const float* w_to_mv   = (const float*)d_in[4];
    const float* w_equi    = (const float*)d_in[5];
    const float* b_equi    = (const float*)d_in[6];
    const float* w_from_mv = (const float*)d_in[7];
    const float* w_up      = (const float*)d_in[8];
    const float* scale     = (const float*)d_in[9];
    float* out = (float*)d_out;

    cudaFuncSetAttribute(fused_kernel, cudaFuncAttributeMaxDynamicSharedMemorySize, SMEM_TOTAL);
    fused_kernel<<<NCTAS, THREADS, SMEM_TOTAL>>>(x, gamma, beta, w_down, w_to_mv, w_equi,
                                                 b_equi, w_from_mv, w_up, scale, out);
}